// round 10
// baseline (speedup 1.0000x reference)
#include <cuda_runtime.h>
#include <cstdint>

#define S_LEN   2048
#define D_MODEL 1024
#define NHEAD   16
#define HDIM    64
#define BATCH   2
#define M_ROWS  (BATCH * S_LEN)   // 4096

// ---------------------------------------------------------------------------
// Scratch (device globals: allocation-free per harness rules)
// ---------------------------------------------------------------------------
__device__ float g_Q[BATCH * NHEAD * S_LEN * HDIM];   // [B*H, S, Hd]
__device__ float g_K[BATCH * NHEAD * S_LEN * HDIM];
__device__ float g_V[BATCH * NHEAD * S_LEN * HDIM];
__device__ float g_C[M_ROWS * D_MODEL];               // attention context [B*S, D]

__device__ __forceinline__ float ex2f_fast(float x) {
    float r;
    asm("ex2.approx.ftz.f32 %0, %1;" : "=f"(r) : "f"(x));
    return r;
}

__device__ __forceinline__ uint32_t smem_u32(const void* p) {
    return (uint32_t)__cvta_generic_to_shared(p);
}

__device__ __forceinline__ void cp_async16(uint32_t dst, const void* src) {
    asm volatile("cp.async.cg.shared.global [%0], [%1], 16;\n"
                 :: "r"(dst), "l"(src));
}
__device__ __forceinline__ void cp_async_commit() {
    asm volatile("cp.async.commit_group;\n" ::: "memory");
}
__device__ __forceinline__ void cp_async_wait_all() {
    asm volatile("cp.async.wait_group 0;\n" ::: "memory");
}

// ---------------------------------------------------------------------------
// SGEMM: C[M=4096, N=1024] = A[4096,1024] @ W[1024,1024]^T + bias
// 128x128 block tile, BK=16, 256 threads, 8x8 micro-tile, double-buffered.
// Loads: 4 lanes per row x 16 bytes = 64B contiguous per row (good sectors).
// MODE 0: QKV (blockIdx.z selects W/bias; scatter into [B*H,S,Hd] layout)
// MODE 1: output projection (A = g_C, row-major output)
// ---------------------------------------------------------------------------
#define SLD 132   // padded smem row length

template <int MODE>
__global__ __launch_bounds__(256, 2)
void sgemm128(const float* __restrict__ A,
              const float* __restrict__ W0, const float* __restrict__ W1,
              const float* __restrict__ W2,
              const float* __restrict__ b0, const float* __restrict__ b1,
              const float* __restrict__ b2,
              float* __restrict__ OutExt)
{
    const float* W;
    const float* bias;
    float* out;
    const float* Ause;

    if (MODE == 0) {
        int z = blockIdx.z;
        W    = (z == 0) ? W0 : (z == 1) ? W1 : W2;
        bias = (z == 0) ? b0 : (z == 1) ? b1 : b2;
        out  = (z == 0) ? g_Q : (z == 1) ? g_K : g_V;
        Ause = A;
    } else {
        W    = W0;
        bias = b0;
        out  = OutExt;
        Ause = g_C;
    }

    __shared__ float As[2][16][SLD];
    __shared__ float Bs[2][16][SLD];

    const int tid = threadIdx.x;
    const int m0  = blockIdx.y * 128;
    const int n0  = blockIdx.x * 128;
    const int ty  = tid >> 4;        // 0..15
    const int tx  = tid & 15;        // 0..15
    const int lr  = tid >> 2;        // 0..63 (row within tile for loads)
    const int lk  = (tid & 3) * 4;   // k offset within BK=16

    const float* Aptr0 = Ause + (size_t)(m0 + lr) * D_MODEL + lk;
    const float* Aptr1 = Aptr0 + (size_t)64 * D_MODEL;
    const float* Wptr0 = W    + (size_t)(n0 + lr) * D_MODEL + lk;
    const float* Wptr1 = Wptr0 + (size_t)64 * D_MODEL;

    // prologue: load k-block 0 into buffer 0
    {
        float4 a0 = *(const float4*)(Aptr0);
        float4 a1 = *(const float4*)(Aptr1);
        float4 w0 = *(const float4*)(Wptr0);
        float4 w1 = *(const float4*)(Wptr1);
        As[0][lk + 0][lr] = a0.x; As[0][lk + 1][lr] = a0.y;
        As[0][lk + 2][lr] = a0.z; As[0][lk + 3][lr] = a0.w;
        As[0][lk + 0][lr + 64] = a1.x; As[0][lk + 1][lr + 64] = a1.y;
        As[0][lk + 2][lr + 64] = a1.z; As[0][lk + 3][lr + 64] = a1.w;
        Bs[0][lk + 0][lr] = w0.x; Bs[0][lk + 1][lr] = w0.y;
        Bs[0][lk + 2][lr] = w0.z; Bs[0][lk + 3][lr] = w0.w;
        Bs[0][lk + 0][lr + 64] = w1.x; Bs[0][lk + 1][lr + 64] = w1.y;
        Bs[0][lk + 2][lr + 64] = w1.z; Bs[0][lk + 3][lr + 64] = w1.w;
    }
    __syncthreads();

    float c[8][8];
#pragma unroll
    for (int i = 0; i < 8; i++)
#pragma unroll
        for (int j = 0; j < 8; j++) c[i][j] = 0.0f;

    const int NKB = D_MODEL / 16;   // 64
    for (int kb = 0; kb < NKB; kb++) {
        const int cur = kb & 1;
        float4 a0, a1, w0, w1;
        if (kb < NKB - 1) {
            const int off = (kb + 1) * 16;
            a0 = *(const float4*)(Aptr0 + off);
            a1 = *(const float4*)(Aptr1 + off);
            w0 = *(const float4*)(Wptr0 + off);
            w1 = *(const float4*)(Wptr1 + off);
        }

#pragma unroll
        for (int kk = 0; kk < 16; kk++) {
            float ar[8], br[8];
            *(float4*)(ar)     = *(const float4*)&As[cur][kk][ty * 8];
            *(float4*)(ar + 4) = *(const float4*)&As[cur][kk][ty * 8 + 4];
            *(float4*)(br)     = *(const float4*)&Bs[cur][kk][tx * 8];
            *(float4*)(br + 4) = *(const float4*)&Bs[cur][kk][tx * 8 + 4];
#pragma unroll
            for (int i = 0; i < 8; i++)
#pragma unroll
                for (int j = 0; j < 8; j++)
                    c[i][j] += ar[i] * br[j];
        }

        if (kb < NKB - 1) {
            const int nxt = cur ^ 1;
            As[nxt][lk + 0][lr] = a0.x; As[nxt][lk + 1][lr] = a0.y;
            As[nxt][lk + 2][lr] = a0.z; As[nxt][lk + 3][lr] = a0.w;
            As[nxt][lk + 0][lr + 64] = a1.x; As[nxt][lk + 1][lr + 64] = a1.y;
            As[nxt][lk + 2][lr + 64] = a1.z; As[nxt][lk + 3][lr + 64] = a1.w;
            Bs[nxt][lk + 0][lr] = w0.x; Bs[nxt][lk + 1][lr] = w0.y;
            Bs[nxt][lk + 2][lr] = w0.z; Bs[nxt][lk + 3][lr] = w0.w;
            Bs[nxt][lk + 0][lr + 64] = w1.x; Bs[nxt][lk + 1][lr + 64] = w1.y;
            Bs[nxt][lk + 2][lr + 64] = w1.z; Bs[nxt][lk + 3][lr + 64] = w1.w;
        }
        __syncthreads();
    }

    // Epilogue (vectorized; 8 consecutive n stay inside one head for MODE 0)
    float bv[8];
    *(float4*)(bv)     = *(const float4*)&bias[n0 + tx * 8];
    *(float4*)(bv + 4) = *(const float4*)&bias[n0 + tx * 8 + 4];

#pragma unroll
    for (int i = 0; i < 8; i++) {
        const int m = m0 + ty * 8 + i;
        const int n = n0 + tx * 8;
        float4 r0, r1;
        r0.x = c[i][0] + bv[0]; r0.y = c[i][1] + bv[1];
        r0.z = c[i][2] + bv[2]; r0.w = c[i][3] + bv[3];
        r1.x = c[i][4] + bv[4]; r1.y = c[i][5] + bv[5];
        r1.z = c[i][6] + bv[6]; r1.w = c[i][7] + bv[7];
        if (MODE == 0) {
            const int b  = m >> 11;
            const int s  = m & 2047;
            const int h  = n >> 6;
            const int hd = n & 63;
            float* p = out + (((size_t)(b * NHEAD + h)) * S_LEN + s) * HDIM + hd;
            *(float4*)(p)     = r0;
            *(float4*)(p + 4) = r1;
        } else {
            float* p = out + (size_t)m * D_MODEL + n;
            *(float4*)(p)     = r0;
            *(float4*)(p + 4) = r1;
        }
    }
}

// ---------------------------------------------------------------------------
// Flash attention (fp32): Br=128, Bc=64, Hd=64, online softmax in registers.
// 256 threads: tx = tid&15 (key group of 4 in scores / hd group of 4 in PV),
//              ty = tid>>4 (q group of 8 in both phases).
// Kts and Pts use XOR swizzle (chunk ^= row>>2) -> no 8-way STS conflicts.
// V loaded via cp.async at loop top, waited just before PV (hidden).
// K prefetched into registers; 3 barriers / tile.
// ---------------------------------------------------------------------------
#define LDQ 132   // Qts/Pts row stride (q dim = 128 + 4)
#define LDK 68    // Kts/Vs  row stride (key dim = 64 + 4)
#define BR  128
#define BC  64

__global__ __launch_bounds__(256, 2)
void flash_attn()
{
    extern __shared__ float sm[];
    float* Qts = sm;                   // [hd=64][q=128]   stride LDQ
    float* Kts = Qts + 64 * LDQ;       // [hd=64][key=64]  stride LDK (swizzled)
    float* Vs  = Kts + 64 * LDK;       // [key=64][hd=64]  stride LDK
    float* Pts = Vs  + 64 * LDK;       // [key=64][q=128]  stride LDQ (swizzled)

    const int tid = threadIdx.x;
    const int bh  = blockIdx.y;        // 0..31
    const int q0  = blockIdx.x * BR;

    const float* Qb = g_Q + ((size_t)bh * S_LEN + q0) * HDIM;
    const float* Kb = g_K + (size_t)bh * S_LEN * HDIM;
    const float* Vb = g_V + (size_t)bh * S_LEN * HDIM;

    const int tx = tid & 15;
    const int ty = tid >> 4;

    // Load Q tile transposed: Qts[hd][q]  (once per block)
    for (int t = tid; t < BR * 16; t += 256) {
        const int q  = t >> 4;
        const int h4 = (t & 15) << 2;
        float4 v = *(const float4*)&Qb[q * HDIM + h4];
        Qts[(h4 + 0) * LDQ + q] = v.x;
        Qts[(h4 + 1) * LDQ + q] = v.y;
        Qts[(h4 + 2) * LDQ + q] = v.z;
        Qts[(h4 + 3) * LDQ + q] = v.w;
    }

    // per-thread K-load coords: 4 chunks, r = key row, h4 = hd offset
    const int kr0 = tid >> 4;          // +16 per chunk
    const int kh4 = tx << 2;

    // Stage K tile 0 into registers
    float4 kf[4];
#pragma unroll
    for (int cnk = 0; cnk < 4; cnk++) {
        const int r = kr0 + cnk * 16;
        kf[cnk] = *(const float4*)&Kb[r * HDIM + kh4];
    }

    float o[8][4];
    float m_run[8], l_run[8];
#pragma unroll
    for (int i = 0; i < 8; i++) {
        m_run[i] = -1e30f;
        l_run[i] = 0.0f;
#pragma unroll
        for (int j = 0; j < 4; j++) o[i][j] = 0.0f;
    }

    const float SCL = 0.125f * 1.4426950408889634f;  // scale * log2(e)

    const uint32_t VsBase = smem_u32(Vs);

    for (int kt = 0; kt < S_LEN / BC; kt++) {
        __syncthreads();   // B1: prior-iter reads of Kts/Vs/Pts done

        // commit staged K (transposed + swizzled) into Kts
#pragma unroll
        for (int cnk = 0; cnk < 4; cnk++) {
            const int r = kr0 + cnk * 16;
            const int rc = (r & 3);
            const int rs = (r >> 2);
            const float kk4[4] = {kf[cnk].x, kf[cnk].y, kf[cnk].z, kf[cnk].w};
#pragma unroll
            for (int j = 0; j < 4; j++) {
                const int hd = kh4 + j;                 // hd>>2 == tx
                const int col = rc | (((rs ^ tx) & 15) << 2);
                Kts[hd * LDK + col] = kk4[j];
            }
        }

        // kick cp.async for V(kt) -> Vs (consumed by PV this iteration)
        {
            const float* Vt = Vb + (size_t)kt * BC * HDIM;
#pragma unroll
            for (int cnk = 0; cnk < 4; cnk++) {
                const int r = kr0 + cnk * 16;
                cp_async16(VsBase + (uint32_t)(r * LDK + kh4) * 4u,
                           &Vt[r * HDIM + kh4]);
            }
            cp_async_commit();
        }
        __syncthreads();   // B2: Kts ready (Qts ready on first iter)

        // prefetch next K tile into registers (overlaps score/softmax)
        if (kt < S_LEN / BC - 1) {
            const float* Kt = Kb + (size_t)(kt + 1) * BC * HDIM;
#pragma unroll
            for (int cnk = 0; cnk < 4; cnk++) {
                const int r = kr0 + cnk * 16;
                kf[cnk] = *(const float4*)&Kt[r * HDIM + kh4];
            }
        }

        // ---- scores: s[ki][qj] = sum_hd K[tx*4+ki][hd] * Q[ty*8+qj][hd] ----
        float s[4][8];
#pragma unroll
        for (int i = 0; i < 4; i++)
#pragma unroll
            for (int j = 0; j < 8; j++) s[i][j] = 0.0f;

#pragma unroll 4
        for (int kk = 0; kk < HDIM; kk++) {
            float4 a0 = *(const float4*)&Qts[kk * LDQ + ty * 8];
            float4 a1 = *(const float4*)&Qts[kk * LDQ + ty * 8 + 4];
            const int kcol = ((tx ^ (kk >> 2)) & 15) << 2;
            float4 b  = *(const float4*)&Kts[kk * LDK + kcol];
            float aq[8] = {a0.x, a0.y, a0.z, a0.w, a1.x, a1.y, a1.z, a1.w};
            float bk[4] = {b.x, b.y, b.z, b.w};
#pragma unroll
            for (int ki = 0; ki < 4; ki++)
#pragma unroll
                for (int qj = 0; qj < 8; qj++)
                    s[ki][qj] += bk[ki] * aq[qj];
        }

        // ---- online softmax in registers; reduce over key dim:
        //      4 local keys then shfl.xor over the 16-lane tx group ----
        float corr_[8];
#pragma unroll
        for (int qj = 0; qj < 8; qj++) {
            float mx = -1e30f;
#pragma unroll
            for (int ki = 0; ki < 4; ki++) {
                const float t = s[ki][qj] * SCL;
                s[ki][qj] = t;
                mx = fmaxf(mx, t);
            }
            mx = fmaxf(mx, __shfl_xor_sync(0xffffffffu, mx, 1));
            mx = fmaxf(mx, __shfl_xor_sync(0xffffffffu, mx, 2));
            mx = fmaxf(mx, __shfl_xor_sync(0xffffffffu, mx, 4));
            mx = fmaxf(mx, __shfl_xor_sync(0xffffffffu, mx, 8));

            const float mn = fmaxf(m_run[qj], mx);
            corr_[qj] = ex2f_fast(m_run[qj] - mn);
            m_run[qj] = mn;

            float ls = 0.0f;
#pragma unroll
            for (int ki = 0; ki < 4; ki++) {
                const float p = ex2f_fast(s[ki][qj] - mn);
                s[ki][qj] = p;
                ls += p;
            }
            ls += __shfl_xor_sync(0xffffffffu, ls, 1);
            ls += __shfl_xor_sync(0xffffffffu, ls, 2);
            ls += __shfl_xor_sync(0xffffffffu, ls, 4);
            ls += __shfl_xor_sync(0xffffffffu, ls, 8);
            l_run[qj] = l_run[qj] * corr_[qj] + ls;
        }

        // write P^T (swizzled): row = key = tx*4+ki; q chunks c = 2*ty + b
#pragma unroll
        for (int ki = 0; ki < 4; ki++) {
            const int row = tx * 4 + ki;
#pragma unroll
            for (int b = 0; b < 2; b++) {
                const int c  = 2 * ty + b;
                const int cc = (c & ~15) | ((c ^ tx) & 15);
                float4 w;
                w.x = s[ki][b * 4 + 0];
                w.y = s[ki][b * 4 + 1];
                w.z = s[ki][b * 4 + 2];
                w.w = s[ki][b * 4 + 3];
                *(float4*)&Pts[row * LDQ + cc * 4] = w;
            }
        }

        // rescale accumulated output by correction
#pragma unroll
        for (int qj = 0; qj < 8; qj++)
#pragma unroll
            for (int hj = 0; hj < 4; hj++)
                o[qj][hj] *= corr_[qj];

        cp_async_wait_all();
        __syncthreads();   // B3: Pts visible, all V copies landed

        // ---- O += P @ V : o[qj][hj] += P[kk][ty*8+qj] * V[kk][tx*4+hj] ----
#pragma unroll 4
        for (int kk = 0; kk < BC; kk++) {
            const int sxor = (kk >> 2) & 15;
            const int c0 = 2 * ty;
            const int c1 = 2 * ty + 1;
            const int cc0 = (c0 & ~15) | ((c0 ^ sxor) & 15);
            const int cc1 = (c1 & ~15) | ((c1 ^ sxor) & 15);
            float4 p0 = *(const float4*)&Pts[kk * LDQ + cc0 * 4];
            float4 p1 = *(const float4*)&Pts[kk * LDQ + cc1 * 4];
            float4 vv = *(const float4*)&Vs[kk * LDK + tx * 4];
            float pq[8] = {p0.x, p0.y, p0.z, p0.w, p1.x, p1.y, p1.z, p1.w};
            float vh[4] = {vv.x, vv.y, vv.z, vv.w};
#pragma unroll
            for (int qj = 0; qj < 8; qj++)
#pragma unroll
                for (int hj = 0; hj < 4; hj++)
                    o[qj][hj] += pq[qj] * vh[hj];
        }
    }

    // epilogue: normalize and write context rows
    const int b = bh >> 4;
    const int h = bh & 15;
#pragma unroll
    for (int qj = 0; qj < 8; qj++) {
        const float inv = 1.0f / l_run[qj];
        const size_t row = (size_t)b * S_LEN + q0 + ty * 8 + qj;
        float4 res;
        res.x = o[qj][0] * inv;
        res.y = o[qj][1] * inv;
        res.z = o[qj][2] * inv;
        res.w = o[qj][3] * inv;
        *(float4*)&g_C[row * D_MODEL + h * HDIM + tx * 4] = res;
    }
}

// ---------------------------------------------------------------------------
// Launch
// ---------------------------------------------------------------------------
extern "C" void kernel_launch(void* const* d_in, const int* in_sizes, int n_in,
                              void* d_out, int out_size)
{
    const float* x  = (const float*)d_in[0];
    const float* Wq = (const float*)d_in[1];
    const float* bq = (const float*)d_in[2];
    const float* Wk = (const float*)d_in[3];
    const float* bk = (const float*)d_in[4];
    const float* Wv = (const float*)d_in[5];
    const float* bv = (const float*)d_in[6];
    const float* Wo = (const float*)d_in[7];
    const float* bo = (const float*)d_in[8];
    float* out = (float*)d_out;

    const int smem_bytes = (64 * LDQ + 64 * LDK + 64 * LDK + 64 * LDQ)
                           * (int)sizeof(float);   // 102400 B
    cudaFuncSetAttribute(flash_attn,
                         cudaFuncAttributeMaxDynamicSharedMemorySize, smem_bytes);

    // 1) fused QKV projections
    {
        dim3 grid(D_MODEL / 128, M_ROWS / 128, 3);
        sgemm128<0><<<grid, 256>>>(x, Wq, Wk, Wv, bq, bk, bv, nullptr);
    }
    // 2) flash attention
    {
        dim3 grid(S_LEN / BR, BATCH * NHEAD);
        flash_attn<<<grid, 256, smem_bytes>>>();
    }
    // 3) output projection
    {
        dim3 grid(D_MODEL / 128, M_ROWS / 128, 1);
        sgemm128<1><<<grid, 256>>>(nullptr, Wo, nullptr, nullptr,
                                   bo, nullptr, nullptr, out);
    }
}

// round 14
// speedup vs baseline: 2.0447x; 2.0447x over previous
#include <cuda_runtime.h>
#include <cuda_bf16.h>
#include <cstdint>

#define S_LEN   2048
#define D_MODEL 1024
#define NHEAD   16
#define HDIM    64
#define BATCH   2
#define M_ROWS  (BATCH * S_LEN)   // 4096

// ---------------------------------------------------------------------------
// Scratch (device globals: allocation-free per harness rules)
// ---------------------------------------------------------------------------
__device__ float g_Q[BATCH * NHEAD * S_LEN * HDIM];   // [B*H, S, Hd]
__device__ float g_K[BATCH * NHEAD * S_LEN * HDIM];
__device__ float g_V[BATCH * NHEAD * S_LEN * HDIM];
__device__ float g_C[M_ROWS * D_MODEL];               // attention context [B*S, D]

__device__ __forceinline__ float ex2f_fast(float x) {
    float r;
    asm("ex2.approx.ftz.f32 %0, %1;" : "=f"(r) : "f"(x));
    return r;
}

__device__ __forceinline__ uint32_t smem_u32(const void* p) {
    return (uint32_t)__cvta_generic_to_shared(p);
}

// ldmatrix x4 (sm_75+, valid on compute_103 virtual target)
__device__ __forceinline__ void ldmx4(uint32_t* r, uint32_t addr) {
    asm volatile("ldmatrix.sync.aligned.m8n8.x4.shared.b16 {%0,%1,%2,%3}, [%4];"
                 : "=r"(r[0]), "=r"(r[1]), "=r"(r[2]), "=r"(r[3])
                 : "r"(addr));
}

// bf16 HMMA m16n8k16 (sm_80+, valid on compute_103 virtual target)
__device__ __forceinline__ void mma16816(float* d, const uint32_t* a,
                                         uint32_t b0, uint32_t b1) {
    asm volatile(
        "mma.sync.aligned.m16n8k16.row.col.f32.bf16.bf16.f32 "
        "{%0,%1,%2,%3}, {%4,%5,%6,%7}, {%8,%9}, {%0,%1,%2,%3};"
        : "+f"(d[0]), "+f"(d[1]), "+f"(d[2]), "+f"(d[3])
        : "r"(a[0]), "r"(a[1]), "r"(a[2]), "r"(a[3]), "r"(b0), "r"(b1));
}

// ---------------------------------------------------------------------------
// Tensor-core GEMM (HMMA bf16 split hi/lo, 3 terms):
//   C[4096,1024] = A[4096,1024] @ W[1024,1024]^T + bias
// Block 128x128, 512 threads (16 warps, warp grid 4x4, warp tile 32x32).
// BK=16, double-buffered smem; tile rows padded to 48B (conflict-free LDSM).
// MODE 0: QKV (blockIdx.z selects W/bias; scatter into [B*H,S,Hd])
// MODE 1: output projection (A = g_C, row-major out)
// ---------------------------------------------------------------------------
#define GROW 48                 // bytes per smem tile row (16 bf16 + 16B pad)
#define GMAT (128 * GROW)       // 6144 B per matrix
#define GSTG (4 * GMAT)         // Ahi, Alo, Bhi, Blo = 24576 B per stage
#define GEMM_SMEM (2 * GSTG)    // 49152 B

template <int MODE>
__global__ __launch_bounds__(512, 1)
void gemm_mma(const float* __restrict__ A,
              const float* __restrict__ W0, const float* __restrict__ W1,
              const float* __restrict__ W2,
              const float* __restrict__ b0, const float* __restrict__ b1,
              const float* __restrict__ b2,
              float* __restrict__ OutExt)
{
    extern __shared__ char gsm[];

    const float* W;
    const float* bias;
    float* out;
    const float* Ause;
    if (MODE == 0) {
        int z = blockIdx.z;
        W    = (z == 0) ? W0 : (z == 1) ? W1 : W2;
        bias = (z == 0) ? b0 : (z == 1) ? b1 : b2;
        out  = (z == 0) ? g_Q : (z == 1) ? g_K : g_V;
        Ause = A;
    } else {
        W = W0; bias = b0; out = OutExt; Ause = g_C;
    }

    const int tid  = threadIdx.x;
    const int lane = tid & 31;
    const int wid  = tid >> 5;          // 0..15
    const int wm   = wid >> 2;          // 0..3  (32-row group)
    const int wn   = wid & 3;           // 0..3  (32-col group)
    const int m0   = blockIdx.y * 128;
    const int n0   = blockIdx.x * 128;

    // ---- staging coords: thread -> (row, 4-float segment) of the k16 chunk
    const int lrow = tid >> 2;          // 0..127
    const int lseg = tid & 3;           // 0..3
    const float* Arow = Ause + (size_t)(m0 + lrow) * D_MODEL + lseg * 4;
    const float* Wrow = W    + (size_t)(n0 + lrow) * D_MODEL + lseg * 4;
    // smem write offsets (8 bytes per store)
    const uint32_t soff = (uint32_t)(lrow * GROW + lseg * 8);

    const uint32_t sb = smem_u32(gsm);

    // ---- ldmatrix read offsets
    // A 16x16 tiles: lanes 0-15 -> rows 0-15 halfcol 0; lanes 16-31 -> halfcol 1
    const uint32_t aoff = (uint32_t)((wm * 32 + (lane & 15)) * GROW
                                     + (lane >> 4) * 16);
    // B: lanes 0-7 n0-7 k0-7 | 8-15 n0-7 k8-15 | 16-23 n8-15 k0-7 | 24-31 n8-15 k8-15
    const uint32_t boff = (uint32_t)((wn * 32 + (lane & 7) + ((lane >> 4) << 3)) * GROW
                                     + ((lane >> 3) & 1) * 16);

    // ---- stage-store helper (hi at mat base, lo at mat base + GMAT)
    auto store_pair = [&](uint32_t matbase, float4 v) {
        float2 p0 = make_float2(v.x, v.y);
        float2 p1 = make_float2(v.z, v.w);
        __nv_bfloat162 h0 = __float22bfloat162_rn(p0);
        __nv_bfloat162 h1 = __float22bfloat162_rn(p1);
        float2 l0f = make_float2(v.x - __bfloat162float(h0.x),
                                 v.y - __bfloat162float(h0.y));
        float2 l1f = make_float2(v.z - __bfloat162float(h1.x),
                                 v.w - __bfloat162float(h1.y));
        __nv_bfloat162 l0 = __float22bfloat162_rn(l0f);
        __nv_bfloat162 l1 = __float22bfloat162_rn(l1f);
        uint2 hv = make_uint2(*(uint32_t*)&h0, *(uint32_t*)&h1);
        uint2 lv = make_uint2(*(uint32_t*)&l0, *(uint32_t*)&l1);
        *(uint2*)(gsm + matbase + soff)        = hv;
        *(uint2*)(gsm + matbase + GMAT + soff) = lv;
    };

    // ---- prologue: stage chunk 0 into buffer 0
    {
        float4 av = *(const float4*)(Arow);
        float4 wv = *(const float4*)(Wrow);
        store_pair(0,        av);    // A hi/lo
        store_pair(2 * GMAT, wv);    // B hi/lo
    }
    __syncthreads();

    float acc[2][4][4];
#pragma unroll
    for (int i = 0; i < 2; i++)
#pragma unroll
        for (int j = 0; j < 4; j++)
#pragma unroll
            for (int k = 0; k < 4; k++) acc[i][j][k] = 0.0f;

    const int NC = D_MODEL / 16;   // 64
    for (int c = 0; c < NC; c++) {
        const uint32_t st  = sb + (uint32_t)(c & 1) * GSTG;
        const uint32_t stg = (uint32_t)((c + 1) & 1) * GSTG;

        float4 av, wv;
        if (c < NC - 1) {
            av = *(const float4*)(Arow + (c + 1) * 16);
            wv = *(const float4*)(Wrow + (c + 1) * 16);
        }

        // ---- fragments
        uint32_t a[2][4], bh[2][4], bl[2][4];
        ldmx4(bh[0], st + 2 * GMAT + boff);
        ldmx4(bh[1], st + 2 * GMAT + boff + 16 * GROW);
        ldmx4(bl[0], st + 3 * GMAT + boff);
        ldmx4(bl[1], st + 3 * GMAT + boff + 16 * GROW);
        ldmx4(a[0],  st + aoff);
        ldmx4(a[1],  st + aoff + 16 * GROW);

        // hi*hi + hi*lo
#pragma unroll
        for (int mt = 0; mt < 2; mt++)
#pragma unroll
            for (int g = 0; g < 2; g++) {
                mma16816(acc[mt][g * 2 + 0], a[mt], bh[g][0], bh[g][1]);
                mma16816(acc[mt][g * 2 + 1], a[mt], bh[g][2], bh[g][3]);
                mma16816(acc[mt][g * 2 + 0], a[mt], bl[g][0], bl[g][1]);
                mma16816(acc[mt][g * 2 + 1], a[mt], bl[g][2], bl[g][3]);
            }

        // lo*hi
        ldmx4(a[0], st + GMAT + aoff);
        ldmx4(a[1], st + GMAT + aoff + 16 * GROW);
#pragma unroll
        for (int mt = 0; mt < 2; mt++)
#pragma unroll
            for (int g = 0; g < 2; g++) {
                mma16816(acc[mt][g * 2 + 0], a[mt], bh[g][0], bh[g][1]);
                mma16816(acc[mt][g * 2 + 1], a[mt], bh[g][2], bh[g][3]);
            }

        // ---- stage next chunk (other buffer; its readers finished at c-1)
        if (c < NC - 1) {
            store_pair(stg,            av);
            store_pair(stg + 2 * GMAT, wv);
        }
        __syncthreads();
    }

    // ---- epilogue: D fragment -> global (+bias)
    const int lq = lane >> 2;          // row within 8
    const int lc = (lane & 3) * 2;     // col pair
#pragma unroll
    for (int mt = 0; mt < 2; mt++) {
#pragma unroll
        for (int g8 = 0; g8 < 4; g8++) {
            const int col = n0 + wn * 32 + g8 * 8 + lc;
            const float bx = bias[col];
            const float by = bias[col + 1];
            const int mr0 = m0 + wm * 32 + mt * 16 + lq;
            const int mr1 = mr0 + 8;
            float2 v0 = make_float2(acc[mt][g8][0] + bx, acc[mt][g8][1] + by);
            float2 v1 = make_float2(acc[mt][g8][2] + bx, acc[mt][g8][3] + by);
            if (MODE == 0) {
                const int h  = col >> 6;
                const int hd = col & 63;
                {
                    const int bb = mr0 >> 11, s = mr0 & 2047;
                    *(float2*)(out + (((size_t)(bb * NHEAD + h)) * S_LEN + s) * HDIM + hd) = v0;
                }
                {
                    const int bb = mr1 >> 11, s = mr1 & 2047;
                    *(float2*)(out + (((size_t)(bb * NHEAD + h)) * S_LEN + s) * HDIM + hd) = v1;
                }
            } else {
                *(float2*)(out + (size_t)mr0 * D_MODEL + col) = v0;
                *(float2*)(out + (size_t)mr1 * D_MODEL + col) = v1;
            }
        }
    }
}

// ---------------------------------------------------------------------------
// Flash attention (fp32) — UNCHANGED from the 1896us R8 kernel.
// Br = Bc = 64, online softmax in registers via shfl; K/V register prefetch.
// ---------------------------------------------------------------------------
#define LDP 68

__global__ __launch_bounds__(256)
void flash_attn()
{
    extern __shared__ float sm[];
    float* Qts = sm;
    float* Kts = Qts + 64 * LDP;
    float* Vs  = Kts + 64 * LDP;
    float* Pts = Vs  + 64 * LDP;

    const int tid = threadIdx.x;
    const int bh  = blockIdx.y;
    const int q0  = blockIdx.x * 64;

    const float* Qb = g_Q + ((size_t)bh * S_LEN + q0) * HDIM;
    const float* Kb = g_K + (size_t)bh * S_LEN * HDIM;
    const float* Vb = g_V + (size_t)bh * S_LEN * HDIM;

    const int ty = tid >> 4;
    const int tx = tid & 15;

    for (int t = tid; t < 1024; t += 256) {
        const int q  = t >> 4;
        const int h4 = (t & 15) << 2;
        float4 v = *(const float4*)&Qb[q * HDIM + h4];
        Qts[(h4 + 0) * LDP + q] = v.x;
        Qts[(h4 + 1) * LDP + q] = v.y;
        Qts[(h4 + 2) * LDP + q] = v.z;
        Qts[(h4 + 3) * LDP + q] = v.w;
    }

    float4 kf[4], vf[4];
#pragma unroll
    for (int cnk = 0; cnk < 4; cnk++) {
        const int t  = tid + cnk * 256;
        const int r  = t >> 4;
        const int h4 = (t & 15) << 2;
        kf[cnk] = *(const float4*)&Kb[r * HDIM + h4];
        vf[cnk] = *(const float4*)&Vb[r * HDIM + h4];
    }

    float o[4][4];
    float m_run[4], l_run[4];
#pragma unroll
    for (int i = 0; i < 4; i++) {
        m_run[i] = -1e30f;
        l_run[i] = 0.0f;
#pragma unroll
        for (int j = 0; j < 4; j++) o[i][j] = 0.0f;
    }

    const float SCL = 0.125f * 1.4426950408889634f;

    for (int kt = 0; kt < S_LEN / 64; kt++) {
        __syncthreads();

#pragma unroll
        for (int cnk = 0; cnk < 4; cnk++) {
            const int t  = tid + cnk * 256;
            const int r  = t >> 4;
            const int h4 = (t & 15) << 2;
            Kts[(h4 + 0) * LDP + r] = kf[cnk].x;
            Kts[(h4 + 1) * LDP + r] = kf[cnk].y;
            Kts[(h4 + 2) * LDP + r] = kf[cnk].z;
            Kts[(h4 + 3) * LDP + r] = kf[cnk].w;
            *(float4*)&Vs[r * LDP + h4] = vf[cnk];
        }
        __syncthreads();

        if (kt < S_LEN / 64 - 1) {
            const float* Kt = Kb + (size_t)(kt + 1) * 64 * HDIM;
            const float* Vt = Vb + (size_t)(kt + 1) * 64 * HDIM;
#pragma unroll
            for (int cnk = 0; cnk < 4; cnk++) {
                const int t  = tid + cnk * 256;
                const int r  = t >> 4;
                const int h4 = (t & 15) << 2;
                kf[cnk] = *(const float4*)&Kt[r * HDIM + h4];
                vf[cnk] = *(const float4*)&Vt[r * HDIM + h4];
            }
        }

        float s[4][4];
#pragma unroll
        for (int i = 0; i < 4; i++)
#pragma unroll
            for (int j = 0; j < 4; j++) s[i][j] = 0.0f;

#pragma unroll 8
        for (int kk = 0; kk < HDIM; kk++) {
            float4 a = *(const float4*)&Qts[kk * LDP + ty * 4];
            float4 b = *(const float4*)&Kts[kk * LDP + tx * 4];
            float aq[4] = {a.x, a.y, a.z, a.w};
            float bk[4] = {b.x, b.y, b.z, b.w};
#pragma unroll
            for (int ki = 0; ki < 4; ki++)
#pragma unroll
                for (int qj = 0; qj < 4; qj++)
                    s[ki][qj] += bk[ki] * aq[qj];
        }

        float corr_[4];
#pragma unroll
        for (int qj = 0; qj < 4; qj++) {
            float mx = -1e30f;
#pragma unroll
            for (int ki = 0; ki < 4; ki++) {
                const float t = s[ki][qj] * SCL;
                s[ki][qj] = t;
                mx = fmaxf(mx, t);
            }
            mx = fmaxf(mx, __shfl_xor_sync(0xffffffffu, mx, 1));
            mx = fmaxf(mx, __shfl_xor_sync(0xffffffffu, mx, 2));
            mx = fmaxf(mx, __shfl_xor_sync(0xffffffffu, mx, 4));
            mx = fmaxf(mx, __shfl_xor_sync(0xffffffffu, mx, 8));

            const float mn = fmaxf(m_run[qj], mx);
            corr_[qj] = ex2f_fast(m_run[qj] - mn);
            m_run[qj] = mn;

            float ls = 0.0f;
#pragma unroll
            for (int ki = 0; ki < 4; ki++) {
                const float p = ex2f_fast(s[ki][qj] - mn);
                s[ki][qj] = p;
                ls += p;
            }
            ls += __shfl_xor_sync(0xffffffffu, ls, 1);
            ls += __shfl_xor_sync(0xffffffffu, ls, 2);
            ls += __shfl_xor_sync(0xffffffffu, ls, 4);
            ls += __shfl_xor_sync(0xffffffffu, ls, 8);
            l_run[qj] = l_run[qj] * corr_[qj] + ls;
        }

#pragma unroll
        for (int ki = 0; ki < 4; ki++)
#pragma unroll
            for (int qj = 0; qj < 4; qj++)
                Pts[(tx * 4 + ki) * LDP + ty * 4 + qj] = s[ki][qj];

#pragma unroll
        for (int qj = 0; qj < 4; qj++)
#pragma unroll
            for (int hj = 0; hj < 4; hj++)
                o[qj][hj] *= corr_[qj];

        __syncthreads();

#pragma unroll 8
        for (int kk = 0; kk < 64; kk++) {
            float4 p  = *(const float4*)&Pts[kk * LDP + ty * 4];
            float4 vv = *(const float4*)&Vs[kk * LDP + tx * 4];
            float pq[4] = {p.x, p.y, p.z, p.w};
            float vh[4] = {vv.x, vv.y, vv.z, vv.w};
#pragma unroll
            for (int qj = 0; qj < 4; qj++)
#pragma unroll
                for (int hj = 0; hj < 4; hj++)
                    o[qj][hj] += pq[qj] * vh[hj];
        }
    }

    const int b = bh >> 4;
    const int h = bh & 15;
#pragma unroll
    for (int qj = 0; qj < 4; qj++) {
        const float inv = 1.0f / l_run[qj];
        const size_t row = (size_t)b * S_LEN + q0 + ty * 4 + qj;
        float4 res;
        res.x = o[qj][0] * inv;
        res.y = o[qj][1] * inv;
        res.z = o[qj][2] * inv;
        res.w = o[qj][3] * inv;
        *(float4*)&g_C[row * D_MODEL + h * HDIM + tx * 4] = res;
    }
}

// ---------------------------------------------------------------------------
// Launch
// ---------------------------------------------------------------------------
extern "C" void kernel_launch(void* const* d_in, const int* in_sizes, int n_in,
                              void* d_out, int out_size)
{
    const float* x  = (const float*)d_in[0];
    const float* Wq = (const float*)d_in[1];
    const float* bq = (const float*)d_in[2];
    const float* Wk = (const float*)d_in[3];
    const float* bk = (const float*)d_in[4];
    const float* Wv = (const float*)d_in[5];
    const float* bv = (const float*)d_in[6];
    const float* Wo = (const float*)d_in[7];
    const float* bo = (const float*)d_in[8];
    float* out = (float*)d_out;

    const int flash_smem = (4 * 64 * LDP) * (int)sizeof(float);
    cudaFuncSetAttribute(flash_attn,
                         cudaFuncAttributeMaxDynamicSharedMemorySize, flash_smem);
    cudaFuncSetAttribute(gemm_mma<0>,
                         cudaFuncAttributeMaxDynamicSharedMemorySize, GEMM_SMEM);
    cudaFuncSetAttribute(gemm_mma<1>,
                         cudaFuncAttributeMaxDynamicSharedMemorySize, GEMM_SMEM);

    // 1) fused QKV projections (HMMA bf16 split)
    {
        dim3 grid(D_MODEL / 128, M_ROWS / 128, 3);
        gemm_mma<0><<<grid, 512, GEMM_SMEM>>>(x, Wq, Wk, Wv, bq, bk, bv, nullptr);
    }
    // 2) flash attention
    {
        dim3 grid(S_LEN / 64, BATCH * NHEAD);
        flash_attn<<<grid, 256, flash_smem>>>();
    }
    // 3) output projection (HMMA bf16 split)
    {
        dim3 grid(D_MODEL / 128, M_ROWS / 128, 1);
        gemm_mma<1><<<grid, 512, GEMM_SMEM>>>(nullptr, Wo, nullptr, nullptr,
                                              bo, nullptr, nullptr, out);
    }
}

// round 15
// speedup vs baseline: 4.0404x; 1.9760x over previous
#include <cuda_runtime.h>
#include <cuda_bf16.h>
#include <cstdint>

#define S_LEN   2048
#define D_MODEL 1024
#define NHEAD   16
#define HDIM    64
#define BATCH   2
#define M_ROWS  (BATCH * S_LEN)   // 4096

// ---------------------------------------------------------------------------
// Scratch (device globals: allocation-free per harness rules)
// ---------------------------------------------------------------------------
__device__ float g_Q[BATCH * NHEAD * S_LEN * HDIM];   // [B*H, S, Hd]
__device__ float g_K[BATCH * NHEAD * S_LEN * HDIM];
__device__ float g_V[BATCH * NHEAD * S_LEN * HDIM];
__device__ float g_C[M_ROWS * D_MODEL];               // attention context [B*S, D]

__device__ __forceinline__ float ex2f_fast(float x) {
    float r;
    asm("ex2.approx.ftz.f32 %0, %1;" : "=f"(r) : "f"(x));
    return r;
}

__device__ __forceinline__ uint32_t smem_u32(const void* p) {
    return (uint32_t)__cvta_generic_to_shared(p);
}

// ldmatrix x4 (sm_75+, valid on compute_103 virtual target)
__device__ __forceinline__ void ldmx4(uint32_t* r, uint32_t addr) {
    asm volatile("ldmatrix.sync.aligned.m8n8.x4.shared.b16 {%0,%1,%2,%3}, [%4];"
                 : "=r"(r[0]), "=r"(r[1]), "=r"(r[2]), "=r"(r[3])
                 : "r"(addr));
}
__device__ __forceinline__ void ldmx4t(uint32_t* r, uint32_t addr) {
    asm volatile("ldmatrix.sync.aligned.m8n8.x4.trans.shared.b16 {%0,%1,%2,%3}, [%4];"
                 : "=r"(r[0]), "=r"(r[1]), "=r"(r[2]), "=r"(r[3])
                 : "r"(addr));
}

// bf16 HMMA m16n8k16 (sm_80+)
__device__ __forceinline__ void mma16816(float* d, const uint32_t* a,
                                         uint32_t b0, uint32_t b1) {
    asm volatile(
        "mma.sync.aligned.m16n8k16.row.col.f32.bf16.bf16.f32 "
        "{%0,%1,%2,%3}, {%4,%5,%6,%7}, {%8,%9}, {%0,%1,%2,%3};"
        : "+f"(d[0]), "+f"(d[1]), "+f"(d[2]), "+f"(d[3])
        : "r"(a[0]), "r"(a[1]), "r"(a[2]), "r"(a[3]), "r"(b0), "r"(b1));
}

// split a float4 into bf16 hi + bf16 residual lo, store as two bf162 pairs
__device__ __forceinline__ void split_store(void* hp, void* lp, float4 v) {
    __nv_bfloat162 h0 = __floats2bfloat162_rn(v.x, v.y);
    __nv_bfloat162 h1 = __floats2bfloat162_rn(v.z, v.w);
    __nv_bfloat162 l0 = __floats2bfloat162_rn(v.x - __low2float(h0),
                                              v.y - __high2float(h0));
    __nv_bfloat162 l1 = __floats2bfloat162_rn(v.z - __low2float(h1),
                                              v.w - __high2float(h1));
    ((__nv_bfloat162*)hp)[0] = h0; ((__nv_bfloat162*)hp)[1] = h1;
    ((__nv_bfloat162*)lp)[0] = l0; ((__nv_bfloat162*)lp)[1] = l1;
}

__device__ __forceinline__ void pack_hilo(float x, float y,
                                          uint32_t& hi, uint32_t& lo) {
    __nv_bfloat162 h = __floats2bfloat162_rn(x, y);
    __nv_bfloat162 l = __floats2bfloat162_rn(x - __low2float(h),
                                             y - __high2float(h));
    hi = *(uint32_t*)&h;
    lo = *(uint32_t*)&l;
}

// ---------------------------------------------------------------------------
// Tensor-core GEMM (HMMA bf16 split hi/lo, 3 terms) — UNCHANGED from R14 WIN.
//   C[4096,1024] = A[4096,1024] @ W[1024,1024]^T + bias
// ---------------------------------------------------------------------------
#define GROW 48
#define GMAT (128 * GROW)
#define GSTG (4 * GMAT)
#define GEMM_SMEM (2 * GSTG)

template <int MODE>
__global__ __launch_bounds__(512, 1)
void gemm_mma(const float* __restrict__ A,
              const float* __restrict__ W0, const float* __restrict__ W1,
              const float* __restrict__ W2,
              const float* __restrict__ b0, const float* __restrict__ b1,
              const float* __restrict__ b2,
              float* __restrict__ OutExt)
{
    extern __shared__ char gsm[];

    const float* W;
    const float* bias;
    float* out;
    const float* Ause;
    if (MODE == 0) {
        int z = blockIdx.z;
        W    = (z == 0) ? W0 : (z == 1) ? W1 : W2;
        bias = (z == 0) ? b0 : (z == 1) ? b1 : b2;
        out  = (z == 0) ? g_Q : (z == 1) ? g_K : g_V;
        Ause = A;
    } else {
        W = W0; bias = b0; out = OutExt; Ause = g_C;
    }

    const int tid  = threadIdx.x;
    const int lane = tid & 31;
    const int wid  = tid >> 5;
    const int wm   = wid >> 2;
    const int wn   = wid & 3;
    const int m0   = blockIdx.y * 128;
    const int n0   = blockIdx.x * 128;

    const int lrow = tid >> 2;
    const int lseg = tid & 3;
    const float* Arow = Ause + (size_t)(m0 + lrow) * D_MODEL + lseg * 4;
    const float* Wrow = W    + (size_t)(n0 + lrow) * D_MODEL + lseg * 4;
    const uint32_t soff = (uint32_t)(lrow * GROW + lseg * 8);

    const uint32_t sb = smem_u32(gsm);

    const uint32_t aoff = (uint32_t)((wm * 32 + (lane & 15)) * GROW
                                     + (lane >> 4) * 16);
    const uint32_t boff = (uint32_t)((wn * 32 + (lane & 7) + ((lane >> 4) << 3)) * GROW
                                     + ((lane >> 3) & 1) * 16);

    auto store_pair = [&](uint32_t matbase, float4 v) {
        split_store(gsm + matbase + soff, gsm + matbase + GMAT + soff, v);
    };

    {
        float4 av = *(const float4*)(Arow);
        float4 wv = *(const float4*)(Wrow);
        store_pair(0,        av);
        store_pair(2 * GMAT, wv);
    }
    __syncthreads();

    float acc[2][4][4];
#pragma unroll
    for (int i = 0; i < 2; i++)
#pragma unroll
        for (int j = 0; j < 4; j++)
#pragma unroll
            for (int k = 0; k < 4; k++) acc[i][j][k] = 0.0f;

    const int NC = D_MODEL / 16;
    for (int c = 0; c < NC; c++) {
        const uint32_t st  = sb + (uint32_t)(c & 1) * GSTG;
        const uint32_t stg = (uint32_t)((c + 1) & 1) * GSTG;

        float4 av, wv;
        if (c < NC - 1) {
            av = *(const float4*)(Arow + (c + 1) * 16);
            wv = *(const float4*)(Wrow + (c + 1) * 16);
        }

        uint32_t a[2][4], bh[2][4], bl[2][4];
        ldmx4(bh[0], st + 2 * GMAT + boff);
        ldmx4(bh[1], st + 2 * GMAT + boff + 16 * GROW);
        ldmx4(bl[0], st + 3 * GMAT + boff);
        ldmx4(bl[1], st + 3 * GMAT + boff + 16 * GROW);
        ldmx4(a[0],  st + aoff);
        ldmx4(a[1],  st + aoff + 16 * GROW);

#pragma unroll
        for (int mt = 0; mt < 2; mt++)
#pragma unroll
            for (int g = 0; g < 2; g++) {
                mma16816(acc[mt][g * 2 + 0], a[mt], bh[g][0], bh[g][1]);
                mma16816(acc[mt][g * 2 + 1], a[mt], bh[g][2], bh[g][3]);
                mma16816(acc[mt][g * 2 + 0], a[mt], bl[g][0], bl[g][1]);
                mma16816(acc[mt][g * 2 + 1], a[mt], bl[g][2], bl[g][3]);
            }

        ldmx4(a[0], st + GMAT + aoff);
        ldmx4(a[1], st + GMAT + aoff + 16 * GROW);
#pragma unroll
        for (int mt = 0; mt < 2; mt++)
#pragma unroll
            for (int g = 0; g < 2; g++) {
                mma16816(acc[mt][g * 2 + 0], a[mt], bh[g][0], bh[g][1]);
                mma16816(acc[mt][g * 2 + 1], a[mt], bh[g][2], bh[g][3]);
            }

        if (c < NC - 1) {
            store_pair(stg,            av);
            store_pair(stg + 2 * GMAT, wv);
        }
        __syncthreads();
    }

    const int lq = lane >> 2;
    const int lc = (lane & 3) * 2;
#pragma unroll
    for (int mt = 0; mt < 2; mt++) {
#pragma unroll
        for (int g8 = 0; g8 < 4; g8++) {
            const int col = n0 + wn * 32 + g8 * 8 + lc;
            const float bx = bias[col];
            const float by = bias[col + 1];
            const int mr0 = m0 + wm * 32 + mt * 16 + lq;
            const int mr1 = mr0 + 8;
            float2 v0 = make_float2(acc[mt][g8][0] + bx, acc[mt][g8][1] + by);
            float2 v1 = make_float2(acc[mt][g8][2] + bx, acc[mt][g8][3] + by);
            if (MODE == 0) {
                const int h  = col >> 6;
                const int hd = col & 63;
                {
                    const int bb = mr0 >> 11, s = mr0 & 2047;
                    *(float2*)(out + (((size_t)(bb * NHEAD + h)) * S_LEN + s) * HDIM + hd) = v0;
                }
                {
                    const int bb = mr1 >> 11, s = mr1 & 2047;
                    *(float2*)(out + (((size_t)(bb * NHEAD + h)) * S_LEN + s) * HDIM + hd) = v1;
                }
            } else {
                *(float2*)(out + (size_t)mr0 * D_MODEL + col) = v0;
                *(float2*)(out + (size_t)mr1 * D_MODEL + col) = v1;
            }
        }
    }
}

// ---------------------------------------------------------------------------
// Flash attention with HMMA split bf16 (3 terms per GEMM stage).
// Br=128 (8 warps x m16 strip), Bc=64, Hd=64.
// smem rows padded to 144B (= 9*16B): ldmatrix conflict-free.
// K row-major (non-trans ldmatrix B), V row-major (ldmatrix.trans B).
// P fragments built in registers from S accumulators (FA2 layout identity).
// ---------------------------------------------------------------------------
#define FROW 144                  // bytes per 64-col bf16 row (64*2 + 16 pad)
#define FQH  0
#define FQL  (128 * FROW)         // 18432
#define FKH  (2 * 128 * FROW)     // 36864
#define FKL  (FKH + 64 * FROW)    // 46080
#define FVH  (FKH + 2 * 64 * FROW)
#define FVL  (FKH + 3 * 64 * FROW)
#define FLASH_SMEM (FKH + 4 * 64 * FROW)   // 73728
#define FLOFF (64 * FROW)         // hi->lo offset for K/V (9216)

__global__ __launch_bounds__(256)
void flash_mma()
{
    extern __shared__ char fsm[];
    const uint32_t sb = smem_u32(fsm);
    const int tid  = threadIdx.x;
    const int lane = tid & 31;
    const int wid  = tid >> 5;          // 0..7, q strip 16*wid
    const int bh   = blockIdx.y;
    const int q0   = blockIdx.x * 128;

    const float* Qb = g_Q + ((size_t)bh * S_LEN + q0) * HDIM;
    const float* Kb = g_K + (size_t)bh * S_LEN * HDIM;
    const float* Vb = g_V + (size_t)bh * S_LEN * HDIM;

    const float SCL = 0.125f * 1.4426950408889634f;   // scale * log2(e)

    // ---- load Q once (scaled), split hi/lo
#pragma unroll
    for (int i = 0; i < 8; i++) {
        const int idx = tid + i * 256;
        const int row = idx >> 4;
        const int c4  = (idx & 15) << 2;
        float4 v = *(const float4*)&Qb[row * HDIM + c4];
        v.x *= SCL; v.y *= SCL; v.z *= SCL; v.w *= SCL;
        split_store(fsm + FQH + row * FROW + c4 * 2,
                    fsm + FQL + row * FROW + c4 * 2, v);
    }

    // ---- ldmatrix base addresses
    // A(Q): m0 rows q0-7 @k0 | m1 rows q8-15 @k0 | m2 q0-7 @k+16B | m3 q8-15 @k+16B
    const uint32_t aQ = sb + FQH
        + (uint32_t)((16 * wid + (lane & 7) + ((lane >> 3) & 1) * 8) * FROW)
        + ((lane >> 4) & 1) * 16;
    // B(K): m0 keys j0-7 @hd0 | m1 keys j0-7 @hd+16B | m2 keys j8-15 @hd0 | m3 ...
    const uint32_t bK = sb + FKH
        + (uint32_t)(((lane & 7) + ((lane >> 4) & 1) * 8) * FROW)
        + ((lane >> 3) & 1) * 16;
    // B(V) trans: m0 keys k0-7 @hd0 | m1 keys k8-15 @hd0 | m2 keys k0-7 @hd+16B | m3 ...
    const uint32_t bV = sb + FVH
        + (uint32_t)(((lane & 7) + ((lane >> 3) & 1) * 8) * FROW)
        + ((lane >> 4) & 1) * 16;

    float oA[8][4];
    float mr[2], lr[2];
#pragma unroll
    for (int j = 0; j < 8; j++)
#pragma unroll
        for (int k = 0; k < 4; k++) oA[j][k] = 0.0f;
    mr[0] = mr[1] = -1e30f;
    lr[0] = lr[1] = 0.0f;

    for (int kt = 0; kt < S_LEN / 64; kt++) {
        __syncthreads();   // prior-iter smem reads done (iter 0: Q writes)

        // ---- load K/V tile, split hi/lo (row-major, padded rows)
        const float* Kt = Kb + (size_t)kt * 64 * HDIM;
        const float* Vt = Vb + (size_t)kt * 64 * HDIM;
#pragma unroll
        for (int i = 0; i < 4; i++) {
            const int idx = tid + i * 256;
            const int row = idx >> 4;
            const int c4  = (idx & 15) << 2;
            float4 kv = *(const float4*)&Kt[row * HDIM + c4];
            float4 vv = *(const float4*)&Vt[row * HDIM + c4];
            split_store(fsm + FKH + row * FROW + c4 * 2,
                        fsm + FKL + row * FROW + c4 * 2, kv);
            split_store(fsm + FVH + row * FROW + c4 * 2,
                        fsm + FVL + row * FROW + c4 * 2, vv);
        }
        __syncthreads();

        // ---- S = Qh*Kh + Qh*Kl + Ql*Kh  (fp32 accumulators, log2 domain)
        float sA[8][4];
#pragma unroll
        for (int j = 0; j < 8; j++)
#pragma unroll
            for (int k = 0; k < 4; k++) sA[j][k] = 0.0f;

#pragma unroll
        for (int kc = 0; kc < 4; kc++) {
            uint32_t qh[4], ql[4];
            ldmx4(qh, aQ + kc * 32);
            ldmx4(ql, aQ + (FQL - FQH) + kc * 32);
#pragma unroll
            for (int jp = 0; jp < 4; jp++) {
                uint32_t kh[4], kl[4];
                const uint32_t ka = bK + jp * (16 * FROW) + kc * 32;
                ldmx4(kh, ka);
                ldmx4(kl, ka + FLOFF);
                mma16816(sA[2 * jp],     qh, kh[0], kh[1]);
                mma16816(sA[2 * jp + 1], qh, kh[2], kh[3]);
                mma16816(sA[2 * jp],     qh, kl[0], kl[1]);
                mma16816(sA[2 * jp + 1], qh, kl[2], kl[3]);
                mma16816(sA[2 * jp],     ql, kh[0], kh[1]);
                mma16816(sA[2 * jp + 1], ql, kh[2], kh[3]);
            }
        }

        // ---- online softmax on fragments (rows lq, lq+8; quad shfl 1,2)
        float corr[2];
#pragma unroll
        for (int r = 0; r < 2; r++) {
            float mx = -1e30f;
#pragma unroll
            for (int j = 0; j < 8; j++)
                mx = fmaxf(mx, fmaxf(sA[j][2 * r], sA[j][2 * r + 1]));
            mx = fmaxf(mx, __shfl_xor_sync(0xffffffffu, mx, 1));
            mx = fmaxf(mx, __shfl_xor_sync(0xffffffffu, mx, 2));

            const float mn = fmaxf(mr[r], mx);
            corr[r] = ex2f_fast(mr[r] - mn);
            mr[r] = mn;

            float ls = 0.0f;
#pragma unroll
            for (int j = 0; j < 8; j++) {
                const float p0 = ex2f_fast(sA[j][2 * r]     - mn);
                const float p1 = ex2f_fast(sA[j][2 * r + 1] - mn);
                sA[j][2 * r] = p0;
                sA[j][2 * r + 1] = p1;
                ls += p0 + p1;
            }
            ls += __shfl_xor_sync(0xffffffffu, ls, 1);
            ls += __shfl_xor_sync(0xffffffffu, ls, 2);
            lr[r] = lr[r] * corr[r] + ls;
        }

        // ---- P fragments (hi + residual lo) straight from S accumulators
        uint32_t ph[4][4], pl[4][4];
#pragma unroll
        for (int kc = 0; kc < 4; kc++) {
            pack_hilo(sA[2 * kc][0],     sA[2 * kc][1],     ph[kc][0], pl[kc][0]);
            pack_hilo(sA[2 * kc][2],     sA[2 * kc][3],     ph[kc][1], pl[kc][1]);
            pack_hilo(sA[2 * kc + 1][0], sA[2 * kc + 1][1], ph[kc][2], pl[kc][2]);
            pack_hilo(sA[2 * kc + 1][2], sA[2 * kc + 1][3], ph[kc][3], pl[kc][3]);
        }

        // ---- rescale O by correction
#pragma unroll
        for (int j = 0; j < 8; j++) {
            oA[j][0] *= corr[0];
            oA[j][1] *= corr[0];
            oA[j][2] *= corr[1];
            oA[j][3] *= corr[1];
        }

        // ---- O += Ph*Vh + Ph*Vl + Pl*Vh
#pragma unroll
        for (int kc = 0; kc < 4; kc++) {
#pragma unroll
            for (int hp = 0; hp < 4; hp++) {
                uint32_t vh[4], vl[4];
                const uint32_t va = bV + kc * (16 * FROW) + hp * 32;
                ldmx4t(vh, va);
                ldmx4t(vl, va + FLOFF);
                mma16816(oA[2 * hp],     ph[kc], vh[0], vh[1]);
                mma16816(oA[2 * hp + 1], ph[kc], vh[2], vh[3]);
                mma16816(oA[2 * hp],     ph[kc], vl[0], vl[1]);
                mma16816(oA[2 * hp + 1], ph[kc], vl[2], vl[3]);
                mma16816(oA[2 * hp],     pl[kc], vh[0], vh[1]);
                mma16816(oA[2 * hp + 1], pl[kc], vh[2], vh[3]);
            }
        }
    }

    // ---- epilogue: normalize, write context
    const int b  = bh >> 4;
    const int h  = bh & 15;
    const int lq = lane >> 2;
    const int lc2 = (lane & 3) * 2;
    const float inv0 = 1.0f / lr[0];
    const float inv1 = 1.0f / lr[1];
    const size_t row0 = (size_t)b * S_LEN + q0 + 16 * wid + lq;
#pragma unroll
    for (int j = 0; j < 8; j++) {
        const int col = h * HDIM + 8 * j + lc2;
        *(float2*)&g_C[row0 * D_MODEL + col] =
            make_float2(oA[j][0] * inv0, oA[j][1] * inv0);
        *(float2*)&g_C[(row0 + 8) * D_MODEL + col] =
            make_float2(oA[j][2] * inv1, oA[j][3] * inv1);
    }
}

// ---------------------------------------------------------------------------
// Launch
// ---------------------------------------------------------------------------
extern "C" void kernel_launch(void* const* d_in, const int* in_sizes, int n_in,
                              void* d_out, int out_size)
{
    const float* x  = (const float*)d_in[0];
    const float* Wq = (const float*)d_in[1];
    const float* bq = (const float*)d_in[2];
    const float* Wk = (const float*)d_in[3];
    const float* bk = (const float*)d_in[4];
    const float* Wv = (const float*)d_in[5];
    const float* bv = (const float*)d_in[6];
    const float* Wo = (const float*)d_in[7];
    const float* bo = (const float*)d_in[8];
    float* out = (float*)d_out;

    cudaFuncSetAttribute(flash_mma,
                         cudaFuncAttributeMaxDynamicSharedMemorySize, FLASH_SMEM);
    cudaFuncSetAttribute(gemm_mma<0>,
                         cudaFuncAttributeMaxDynamicSharedMemorySize, GEMM_SMEM);
    cudaFuncSetAttribute(gemm_mma<1>,
                         cudaFuncAttributeMaxDynamicSharedMemorySize, GEMM_SMEM);

    // 1) fused QKV projections (HMMA bf16 split)
    {
        dim3 grid(D_MODEL / 128, M_ROWS / 128, 3);
        gemm_mma<0><<<grid, 512, GEMM_SMEM>>>(x, Wq, Wk, Wv, bq, bk, bv, nullptr);
    }
    // 2) flash attention (HMMA bf16 split)
    {
        dim3 grid(S_LEN / 128, BATCH * NHEAD);
        flash_mma<<<grid, 256, FLASH_SMEM>>>();
    }
    // 3) output projection (HMMA bf16 split)
    {
        dim3 grid(D_MODEL / 128, M_ROWS / 128, 1);
        gemm_mma<1><<<grid, 512, GEMM_SMEM>>>(nullptr, Wo, nullptr, nullptr,
                                              bo, nullptr, nullptr, out);
    }
}